// round 1
// baseline (speedup 1.0000x reference)
#include <cuda_runtime.h>

// Problem shape (fixed by the dataset)
constexpr int Bsz = 4;
constexpr int Tsz = 2048;
constexpr int Hsz = 2048;
constexpr int BT  = Bsz * Tsz;                 // 8192 GEMM rows
constexpr long TOT = (long)BT * Hsz;           // 16,777,216 elements

// ---------------- scratch (device globals; no cudaMalloc allowed) ----------
__device__ float g_kx[BT * Hsz];
__device__ float g_vx[BT * Hsz];
__device__ float g_rx[BT * Hsz];
__device__ float g_k [BT * Hsz];
__device__ float g_v [BT * Hsz];
__device__ float g_r [BT * Hsz];
__device__ float g_rc[BT * Hsz];

// ---------------- 1) token-shift + three mixes (fused, float4) -------------
__global__ void mix_kernel(const float4* __restrict__ hid,
                           const float4* __restrict__ sx,
                           const float4* __restrict__ tmk4,
                           const float4* __restrict__ tmv4,
                           const float4* __restrict__ tmr4)
{
    int i = blockIdx.x * blockDim.x + threadIdx.x;     // float4 index
    if (i >= (int)(TOT / 4)) return;
    int e  = i * 4;
    int h4 = (e % Hsz) >> 2;
    int bt = e / Hsz;
    int t  = bt % Tsz;
    int b  = bt / Tsz;

    float4 cur  = hid[i];
    float4 prev = (t == 0) ? sx[(b * Hsz >> 2) + h4] : hid[i - (Hsz >> 2)];
    float4 mk = tmk4[h4], mv = tmv4[h4], mr = tmr4[h4];

    float4 okx, ovx, orx;
#define MIX1(o, m, comp) o.comp = fmaf(cur.comp - prev.comp, m.comp, prev.comp)
    MIX1(okx, mk, x); MIX1(okx, mk, y); MIX1(okx, mk, z); MIX1(okx, mk, w);
    MIX1(ovx, mv, x); MIX1(ovx, mv, y); MIX1(ovx, mv, z); MIX1(ovx, mv, w);
    MIX1(orx, mr, x); MIX1(orx, mr, y); MIX1(orx, mr, z); MIX1(orx, mr, w);
#undef MIX1
    reinterpret_cast<float4*>(g_kx)[i] = okx;
    reinterpret_cast<float4*>(g_vx)[i] = ovx;
    reinterpret_cast<float4*>(g_rx)[i] = orx;
}

// ---------------- 2) fp32 tiled SGEMM: C[M,N] = A[M,K] * B[K,N] ------------
// BM=BN=128, BK=8, 256 threads, 8x8 micro-tile per thread.
constexpr int BM = 128, BN = 128, BK = 8, TM = 8, TN = 8;

__global__ __launch_bounds__(256, 2)
void sgemm_kernel(const float* __restrict__ A,
                  const float* __restrict__ Bm,
                  float* __restrict__ C,
                  int M, int N, int K)
{
    __shared__ float As[BK][BM];
    __shared__ float Bs[BK][BN];

    const int tid  = threadIdx.x;
    const int brow = blockIdx.y * BM;
    const int bcol = blockIdx.x * BN;

    // A tile loader: one float4 per thread (128 rows x 2 float4 per row)
    const int arow = tid >> 1;
    const int acol = (tid & 1) * 4;
    // B tile loader: 8 rows x 32 float4
    const int browi = tid >> 5;
    const int bcoli = (tid & 31) * 4;

    const float* Aptr = A  + (long)(brow + arow) * K + acol;
    const float* Bptr = Bm + (long)browi * N + bcol + bcoli;

    const int tx = (tid & 15) * TN;
    const int ty = (tid >> 4) * TM;

    float acc[TM][TN] = {};
    float ra[TM], rb[TN];

    for (int k0 = 0; k0 < K; k0 += BK) {
        float4 av = *reinterpret_cast<const float4*>(Aptr); Aptr += BK;
        float4 bv = *reinterpret_cast<const float4*>(Bptr); Bptr += (long)BK * N;

        As[acol + 0][arow] = av.x;
        As[acol + 1][arow] = av.y;
        As[acol + 2][arow] = av.z;
        As[acol + 3][arow] = av.w;
        *reinterpret_cast<float4*>(&Bs[browi][bcoli]) = bv;
        __syncthreads();

#pragma unroll
        for (int k = 0; k < BK; k++) {
#pragma unroll
            for (int i = 0; i < TM; i++) ra[i] = As[k][ty + i];
#pragma unroll
            for (int j = 0; j < TN; j++) rb[j] = Bs[k][tx + j];
#pragma unroll
            for (int i = 0; i < TM; i++)
#pragma unroll
                for (int j = 0; j < TN; j++)
                    acc[i][j] = fmaf(ra[i], rb[j], acc[i][j]);
        }
        __syncthreads();
    }

#pragma unroll
    for (int i = 0; i < TM; i++) {
        float* crow = C + (long)(brow + ty + i) * N + bcol + tx;
#pragma unroll
        for (int j = 0; j < TN; j += 4) {
            float4 o = make_float4(acc[i][j], acc[i][j+1], acc[i][j+2], acc[i][j+3]);
            *reinterpret_cast<float4*>(crow + j) = o;
        }
    }
}

// ---------------- 3) WKV scan (sequential in T, parallel over B*H) ---------
__global__ void scan_kernel(const float* __restrict__ hidden,
                            const float* __restrict__ aa0,
                            const float* __restrict__ bb0,
                            const float* __restrict__ pp0,
                            const float* __restrict__ tdecay,
                            const float* __restrict__ tfirst,
                            float* __restrict__ dout)
{
    int gid = blockIdx.x * blockDim.x + threadIdx.x;
    if (gid >= Bsz * Hsz) return;
    const int b = gid / Hsz;
    const int h = gid % Hsz;

    float a  = aa0[gid];
    float bb = bb0[gid];
    float p  = pp0[gid];
    const float u = tfirst[h];
    const float w = -expf(tdecay[h]);

    const long base = (long)b * Tsz * Hsz + h;
    const float* kp = g_k  + base;
    const float* vp = g_v  + base;
    const float* rp = g_r  + base;
    float*       cp = g_rc + base;

    float kk = kp[0], vv = vp[0], rr = rp[0];
#pragma unroll 2
    for (int t = 0; t < Tsz; t++) {
        float kn = 0.f, vn = 0.f, rn = 0.f;
        if (t + 1 < Tsz) {          // prefetch next step (off the dep chain)
            long off = (long)(t + 1) * Hsz;
            kn = kp[off]; vn = vp[off]; rn = rp[off];
        }
        // output c_t
        float ww = u + kk;
        float q  = fmaxf(p, ww);
        float e1 = expf(p - q);
        float e2 = expf(ww - q);
        float c  = (e1 * a + e2 * vv) / (e1 * bb + e2);
        float sr = 1.0f / (1.0f + expf(-rr));
        cp[(long)t * Hsz] = sr * c;
        // state update
        float ww2 = w + p;
        float q2  = fmaxf(ww2, kk);
        float f1  = expf(ww2 - q2);
        float f2  = expf(kk - q2);
        a  = f1 * a  + f2 * vv;
        bb = f1 * bb + f2;
        p  = q2;
        kk = kn; vv = vn; rr = rn;
    }

    // tail of d_out: hidden_last, aa, bb, pp
    float* st = dout + TOT;
    st[gid]                 = hidden[(long)b * Tsz * Hsz + (long)(Tsz - 1) * Hsz + h];
    st[Bsz * Hsz     + gid] = a;
    st[2 * Bsz * Hsz + gid] = bb;
    st[3 * Bsz * Hsz + gid] = p;
}

// ---------------- launch ----------------------------------------------------
extern "C" void kernel_launch(void* const* d_in, const int* in_sizes, int n_in,
                              void* d_out, int out_size)
{
    const float* hidden = (const float*)d_in[0];
    const float* sx     = (const float*)d_in[1];
    const float* aa     = (const float*)d_in[2];
    const float* bb     = (const float*)d_in[3];
    const float* pp     = (const float*)d_in[4];
    const float* td     = (const float*)d_in[5];
    const float* tf     = (const float*)d_in[6];
    const float* tmk    = (const float*)d_in[7];
    const float* tmv    = (const float*)d_in[8];
    const float* tmr    = (const float*)d_in[9];
    const float* Wk     = (const float*)d_in[10];
    const float* Wv     = (const float*)d_in[11];
    const float* Wr     = (const float*)d_in[12];
    const float* Wo     = (const float*)d_in[13];
    float* out = (float*)d_out;

    void *p_kx, *p_vx, *p_rx, *p_k, *p_v, *p_r, *p_rc;
    cudaGetSymbolAddress(&p_kx, g_kx);
    cudaGetSymbolAddress(&p_vx, g_vx);
    cudaGetSymbolAddress(&p_rx, g_rx);
    cudaGetSymbolAddress(&p_k,  g_k);
    cudaGetSymbolAddress(&p_v,  g_v);
    cudaGetSymbolAddress(&p_r,  g_r);
    cudaGetSymbolAddress(&p_rc, g_rc);

    // 1) mixes
    {
        int n4 = (int)(TOT / 4);
        mix_kernel<<<(n4 + 255) / 256, 256>>>(
            (const float4*)hidden, (const float4*)sx,
            (const float4*)tmk, (const float4*)tmv, (const float4*)tmr);
    }

    // 2) three projection GEMMs
    dim3 grid(Hsz / BN, BT / BM), blk(256);
    sgemm_kernel<<<grid, blk>>>((const float*)p_kx, Wk, (float*)p_k, BT, Hsz, Hsz);
    sgemm_kernel<<<grid, blk>>>((const float*)p_vx, Wv, (float*)p_v, BT, Hsz, Hsz);
    sgemm_kernel<<<grid, blk>>>((const float*)p_rx, Wr, (float*)p_r, BT, Hsz, Hsz);

    // 3) scan (+ sigmoid(r)*c, final states, hidden_last)
    scan_kernel<<<(Bsz * Hsz) / 128, 128>>>(hidden, aa, bb, pp, td, tf, out);

    // 4) output projection
    sgemm_kernel<<<grid, blk>>>((const float*)p_rc, Wo, out, BT, Hsz, Hsz);
}

// round 3
// speedup vs baseline: 4.3515x; 4.3515x over previous
#include <cuda_runtime.h>
#include <cuda_fp16.h>
#include <cstdint>

// Problem shape (fixed by the dataset)
constexpr int Bsz = 4;
constexpr int Tsz = 2048;
constexpr int Hsz = 2048;
constexpr int BT  = Bsz * Tsz;                 // 8192 GEMM rows
constexpr long TOT = (long)BT * Hsz;           // 16,777,216 elements

// ---------------- scratch (device globals; no cudaMalloc allowed) ----------
__device__ __half g_kx[BT * Hsz];
__device__ __half g_vx[BT * Hsz];
__device__ __half g_rx[BT * Hsz];
__device__ float  g_k [BT * Hsz];
__device__ float  g_v [BT * Hsz];
__device__ float  g_r [BT * Hsz];
__device__ __half g_rc[BT * Hsz];
// transposed fp16 weights: Wt[n][k] = W[k][n]
__device__ __half g_wk[Hsz * Hsz];
__device__ __half g_wv[Hsz * Hsz];
__device__ __half g_wr[Hsz * Hsz];
__device__ __half g_wo[Hsz * Hsz];

// ---------------- PTX helpers ----------------------------------------------
__device__ __forceinline__ uint32_t smem_u32(const void* p) {
    uint32_t a;
    asm("{ .reg .u64 t; cvta.to.shared.u64 t, %1; cvt.u32.u64 %0, t; }" : "=r"(a) : "l"(p));
    return a;
}
#define SW128(off) ((off) ^ (((off) >> 3) & 0x70))
#define CP_ASYNC16(dst, src) \
    asm volatile("cp.async.cg.shared.global [%0], [%1], 16;" :: "r"(dst), "l"(src))
#define CP_COMMIT() asm volatile("cp.async.commit_group;" ::: "memory")

__device__ __forceinline__ void ldsm_x4(uint32_t& r0, uint32_t& r1,
                                        uint32_t& r2, uint32_t& r3, uint32_t addr) {
    asm volatile("ldmatrix.sync.aligned.m8n8.x4.shared.b16 {%0,%1,%2,%3}, [%4];"
                 : "=r"(r0), "=r"(r1), "=r"(r2), "=r"(r3) : "r"(addr));
}
__device__ __forceinline__ void mma16816(float* d, const uint32_t* a, const uint32_t* b) {
    asm volatile(
        "mma.sync.aligned.m16n8k16.row.col.f32.f16.f16.f32 "
        "{%0,%1,%2,%3}, {%4,%5,%6,%7}, {%8,%9}, {%0,%1,%2,%3};"
        : "+f"(d[0]), "+f"(d[1]), "+f"(d[2]), "+f"(d[3])
        : "r"(a[0]), "r"(a[1]), "r"(a[2]), "r"(a[3]), "r"(b[0]), "r"(b[1]));
}

// ---------------- 1) token-shift + mixes (fp16 emit) ------------------------
__global__ void mix_kernel(const float4* __restrict__ hid,
                           const float4* __restrict__ sx,
                           const float4* __restrict__ tmk4,
                           const float4* __restrict__ tmv4,
                           const float4* __restrict__ tmr4)
{
    int i = blockIdx.x * blockDim.x + threadIdx.x;     // float4 index
    if (i >= (int)(TOT / 4)) return;
    long e = (long)i * 4;
    int h4 = (int)(e % Hsz) >> 2;
    int bt = (int)(e / Hsz);
    int t  = bt % Tsz;
    int b  = bt / Tsz;

    float4 cur  = hid[i];
    float4 prev = (t == 0) ? sx[(b * Hsz >> 2) + h4] : hid[i - (Hsz >> 2)];
    float4 mk = tmk4[h4], mv = tmv4[h4], mr = tmr4[h4];

#define MIXOUT(dst, m) { \
    float4 o; \
    o.x = fmaf(cur.x - prev.x, m.x, prev.x); \
    o.y = fmaf(cur.y - prev.y, m.y, prev.y); \
    o.z = fmaf(cur.z - prev.z, m.z, prev.z); \
    o.w = fmaf(cur.w - prev.w, m.w, prev.w); \
    __half2 p0 = __floats2half2_rn(o.x, o.y); \
    __half2 p1 = __floats2half2_rn(o.z, o.w); \
    *reinterpret_cast<__half2*>(dst + e)     = p0; \
    *reinterpret_cast<__half2*>(dst + e + 2) = p1; }
    MIXOUT(g_kx, mk);
    MIXOUT(g_vx, mv);
    MIXOUT(g_rx, mr);
#undef MIXOUT
}

// ---------------- 2) weight transpose + fp16 convert -------------------------
__global__ void wsplit_kernel(const float* __restrict__ W, __half* __restrict__ Tt)
{
    __shared__ float tile[32][33];
    int x = blockIdx.x * 32 + threadIdx.x;   // input col n
    int y = blockIdx.y * 32 + threadIdx.y;   // input row k
#pragma unroll
    for (int j = 0; j < 32; j += 8)
        tile[threadIdx.y + j][threadIdx.x] = W[(long)(y + j) * Hsz + x];
    __syncthreads();
    int ox = blockIdx.y * 32 + threadIdx.x;  // output col = k
    int oy = blockIdx.x * 32 + threadIdx.y;  // output row = n
#pragma unroll
    for (int j = 0; j < 32; j += 8)
        Tt[(long)(oy + j) * Hsz + ox] = __float2half_rn(tile[threadIdx.x][threadIdx.y + j]);
}

// ---------------- 3) HMMA fp16 GEMM: C[M,N] = A[M,K] * Bt[N,K]^T -------------
// 128x128 CTA tile, BK=64, cp.async double buffer, ldmatrix + mma.m16n8k16.
constexpr int GBM = 128, GBN = 128, GBK = 64;
constexpr int NKC = Hsz / GBK;                 // 32 chunks
constexpr int TILEB = GBM * 128;               // 16 KB per matrix tile (128B rows)
constexpr int STAGEB = 2 * TILEB;              // 32 KB per stage
constexpr int DSMEM = 2 * STAGEB;              // 64 KB

__device__ __forceinline__ void load_chunk(uint32_t sA, uint32_t sB,
                                           const __half* A, const __half* Bt,
                                           int brow, int bcol, int kc, int tid)
{
    const int k0 = kc * GBK;
#pragma unroll
    for (int j = 0; j < 4; j++) {              // 1024 16B chunks per matrix
        int cid = tid + j * 256;
        int r = cid >> 3, c = cid & 7;
        uint32_t so = SW128((uint32_t)(r * 128 + c * 16));
        CP_ASYNC16(sA + so, A  + (long)(brow + r) * Hsz + k0 + c * 8);
        CP_ASYNC16(sB + so, Bt + (long)(bcol + r) * Hsz + k0 + c * 8);
    }
}

__global__ __launch_bounds__(256, 2)
void hgemm_kernel(const __half* __restrict__ A,
                  const __half* __restrict__ Bt,
                  float* __restrict__ C)
{
    extern __shared__ char dsm[];
    const uint32_t sbase = smem_u32(dsm);

    const int tid = threadIdx.x;
    const int wid = tid >> 5;
    const int lane = tid & 31;
    const int brow = blockIdx.y * GBM;
    const int bcol = blockIdx.x * GBN;

    const int warp_m = (wid & 1) * 64;         // 2 warps along M
    const int warp_n = (wid >> 1) * 32;        // 4 warps along N

    float acc[4][4][4] = {};                   // [mt][nt][frag]

    // precomputed ldmatrix intra-tile offsets (within a 16KB tile, pre-swizzle base terms)
    const int a_row = warp_m + (lane & 15);            // + mt*16
    const int a_kb  = (lane >> 4) << 4;                // + ks*32
    const int b_row = warp_n + ((lane >> 4) << 3) + (lane & 7);   // + bp*16
    const int b_kb  = ((lane >> 3) & 1) << 4;          // + ks*32

    // prologue
    load_chunk(sbase, sbase + TILEB, A, Bt, brow, bcol, 0, tid);
    CP_COMMIT();

    for (int kc = 0; kc < NKC; kc++) {
        if (kc + 1 < NKC) {
            uint32_t st = sbase + (uint32_t)((kc + 1) & 1) * STAGEB;
            load_chunk(st, st + TILEB, A, Bt, brow, bcol, kc + 1, tid);
            CP_COMMIT();
            asm volatile("cp.async.wait_group 1;" ::: "memory");
        } else {
            asm volatile("cp.async.wait_group 0;" ::: "memory");
        }
        __syncthreads();

        const uint32_t sA = sbase + (uint32_t)(kc & 1) * STAGEB;
        const uint32_t sB = sA + TILEB;

#pragma unroll
        for (int ks = 0; ks < 4; ks++) {
            uint32_t a[4][4], b[2][4];
#pragma unroll
            for (int mt = 0; mt < 4; mt++) {
                uint32_t byte = (uint32_t)((a_row + mt * 16) * 128 + ks * 32 + a_kb);
                ldsm_x4(a[mt][0], a[mt][1], a[mt][2], a[mt][3], sA + SW128(byte));
            }
#pragma unroll
            for (int bp = 0; bp < 2; bp++) {
                uint32_t byte = (uint32_t)((b_row + bp * 16) * 128 + ks * 32 + b_kb);
                ldsm_x4(b[bp][0], b[bp][1], b[bp][2], b[bp][3], sB + SW128(byte));
            }
#pragma unroll
            for (int mt = 0; mt < 4; mt++)
#pragma unroll
                for (int nt = 0; nt < 4; nt++)
                    mma16816(acc[mt][nt], a[mt], &b[nt >> 1][(nt & 1) * 2]);
        }
        __syncthreads();
    }

    // epilogue: direct fp32 stores
#pragma unroll
    for (int mt = 0; mt < 4; mt++) {
        int row0 = brow + warp_m + mt * 16 + (lane >> 2);
#pragma unroll
        for (int nt = 0; nt < 4; nt++) {
            int col = bcol + warp_n + nt * 8 + (lane & 3) * 2;
            float2 lo = make_float2(acc[mt][nt][0], acc[mt][nt][1]);
            float2 hi = make_float2(acc[mt][nt][2], acc[mt][nt][3]);
            *reinterpret_cast<float2*>(C + (long)row0 * Hsz + col)       = lo;
            *reinterpret_cast<float2*>(C + (long)(row0 + 8) * Hsz + col) = hi;
        }
    }
}

// ---------------- 4) WKV scan (sequential in T, parallel over B*H) ----------
__global__ void scan_kernel(const float* __restrict__ hidden,
                            const float* __restrict__ aa0,
                            const float* __restrict__ bb0,
                            const float* __restrict__ pp0,
                            const float* __restrict__ tdecay,
                            const float* __restrict__ tfirst,
                            float* __restrict__ dout)
{
    int gid = blockIdx.x * blockDim.x + threadIdx.x;
    if (gid >= Bsz * Hsz) return;
    const int b = gid / Hsz;
    const int h = gid % Hsz;

    float a  = aa0[gid];
    float bb = bb0[gid];
    float p  = pp0[gid];
    const float u = tfirst[h];
    const float w = -expf(tdecay[h]);

    const long base = (long)b * Tsz * Hsz + h;
    const float* kp = g_k + base;
    const float* vp = g_v + base;
    const float* rp = g_r + base;
    __half* cp = g_rc + base;

    float kk = kp[0], vv = vp[0], rr = rp[0];
#pragma unroll 2
    for (int t = 0; t < Tsz; t++) {
        float kn = 0.f, vn = 0.f, rn = 0.f;
        if (t + 1 < Tsz) {          // prefetch next step (off the dep chain)
            long off = (long)(t + 1) * Hsz;
            kn = kp[off]; vn = vp[off]; rn = rp[off];
        }
        float ww = u + kk;
        float q  = fmaxf(p, ww);
        float e1 = expf(p - q);
        float e2 = expf(ww - q);
        float c  = (e1 * a + e2 * vv) / (e1 * bb + e2);
        float sr = 1.0f / (1.0f + expf(-rr));
        cp[(long)t * Hsz] = __float2half_rn(sr * c);
        float ww2 = w + p;
        float q2  = fmaxf(ww2, kk);
        float f1  = expf(ww2 - q2);
        float f2  = expf(kk - q2);
        a  = f1 * a  + f2 * vv;
        bb = f1 * bb + f2;
        p  = q2;
        kk = kn; vv = vn; rr = rn;
    }

    float* st = dout + TOT;
    st[gid]                 = hidden[(long)b * Tsz * Hsz + (long)(Tsz - 1) * Hsz + h];
    st[Bsz * Hsz     + gid] = a;
    st[2 * Bsz * Hsz + gid] = bb;
    st[3 * Bsz * Hsz + gid] = p;
}

// ---------------- launch ----------------------------------------------------
extern "C" void kernel_launch(void* const* d_in, const int* in_sizes, int n_in,
                              void* d_out, int out_size)
{
    const float* hidden = (const float*)d_in[0];
    const float* sx     = (const float*)d_in[1];
    const float* aa     = (const float*)d_in[2];
    const float* bb     = (const float*)d_in[3];
    const float* pp     = (const float*)d_in[4];
    const float* td     = (const float*)d_in[5];
    const float* tf     = (const float*)d_in[6];
    const float* tmk    = (const float*)d_in[7];
    const float* tmv    = (const float*)d_in[8];
    const float* tmr    = (const float*)d_in[9];
    const float* Wk     = (const float*)d_in[10];
    const float* Wv     = (const float*)d_in[11];
    const float* Wr     = (const float*)d_in[12];
    const float* Wo     = (const float*)d_in[13];
    float* out = (float*)d_out;

    cudaFuncSetAttribute(hgemm_kernel, cudaFuncAttributeMaxDynamicSharedMemorySize, DSMEM);

    void *p_kx, *p_vx, *p_rx, *p_k, *p_v, *p_r, *p_rc;
    void *p_wk, *p_wv, *p_wr, *p_wo;
    cudaGetSymbolAddress(&p_kx, g_kx); cudaGetSymbolAddress(&p_vx, g_vx);
    cudaGetSymbolAddress(&p_rx, g_rx);
    cudaGetSymbolAddress(&p_k, g_k); cudaGetSymbolAddress(&p_v, g_v);
    cudaGetSymbolAddress(&p_r, g_r); cudaGetSymbolAddress(&p_rc, g_rc);
    cudaGetSymbolAddress(&p_wk, g_wk); cudaGetSymbolAddress(&p_wv, g_wv);
    cudaGetSymbolAddress(&p_wr, g_wr); cudaGetSymbolAddress(&p_wo, g_wo);

    // 1) mixes (fp16 emit)
    {
        int n4 = (int)(TOT / 4);
        mix_kernel<<<(n4 + 255) / 256, 256>>>(
            (const float4*)hidden, (const float4*)sx,
            (const float4*)tmk, (const float4*)tmv, (const float4*)tmr);
    }

    // 2) weight transpose + fp16 convert
    {
        dim3 tg(Hsz / 32, Hsz / 32), tb(32, 8);
        wsplit_kernel<<<tg, tb>>>(Wk, (__half*)p_wk);
        wsplit_kernel<<<tg, tb>>>(Wv, (__half*)p_wv);
        wsplit_kernel<<<tg, tb>>>(Wr, (__half*)p_wr);
        wsplit_kernel<<<tg, tb>>>(Wo, (__half*)p_wo);
    }

    // 3) three projection GEMMs (HMMA fp16)
    dim3 gg(Hsz / GBN, BT / GBM), gb(256);
    hgemm_kernel<<<gg, gb, DSMEM>>>((const __half*)p_kx, (const __half*)p_wk, (float*)p_k);
    hgemm_kernel<<<gg, gb, DSMEM>>>((const __half*)p_vx, (const __half*)p_wv, (float*)p_v);
    hgemm_kernel<<<gg, gb, DSMEM>>>((const __half*)p_rx, (const __half*)p_wr, (float*)p_r);

    // 4) scan (+ sigmoid(r)*c fp16 emit, final states, hidden_last)
    scan_kernel<<<(Bsz * Hsz) / 128, 128>>>(hidden, aa, bb, pp, td, tf, out);

    // 5) output projection
    hgemm_kernel<<<gg, gb, DSMEM>>>((const __half*)p_rc, (const __half*)p_wo, out);
}